// round 16
// baseline (speedup 1.0000x reference)
#include <cuda_runtime.h>
#include <cuda_fp16.h>
#include <math.h>
#include <stdint.h>

#define BB 8
#define NN 2048
#define DD 256
#define BN_EPS 1e-5f
#define SELU_ALPHA 1.6732632423543772f
#define SELU_SCALE 1.0507009873554805f

// ===========================================================================
// Scratch (device globals)
// ===========================================================================
__device__ __half g_attn[(size_t)BB * NN * NN];      // 67 MB, UNNORMALIZED exp(s)
__device__ __half g_xw[(size_t)BB * NN * DD];
__device__ __half g_x_h[(size_t)BB * NN * DD];
__device__ __half g_agg[(size_t)BB * NN * DD];
__device__ __half g_outh[(size_t)BB * NN * DD];
__device__ __half g_watt_h[DD * DD];
__device__ __half g_wres_h[DD * DD];
__device__ float g_prow[BB * 16 * 128 * 16];         // [b][rb][row][cb] (1 MB)
__device__ float g_psum[256 * 256];
__device__ float g_psumsq[256 * 256];
__device__ float g_scale[256];
__device__ float g_shift[256];

// ===========================================================================
// smem layouts:
// m-major tile: rows x 64 k fp16, 128B rows, chunk' = c ^ (r&7), c in 0..7
// k-major tile: 64 rows(k) x 128 cols(n), 256B rows, chunk' = c ^ (r&7)
// k_scores: stage = A128(16K)+B128(16K)=32K x3 = 96K (occ 2)
// k_agg/k_out: stage = A64(8K)+B(16K)=24K x3 = 72K (occ 3)
// ===========================================================================
#define TILE64_B 16384
#define STG64_B  32768
#define SMEM_SC  (3 * STG64_B)          // 98304
#define TILEA_S  8192
#define STG_S    24576
#define SMEM_S   (3 * STG_S)            // 73728
#define SMEM_AGS (SMEM_S + 256)         // + invZ (64 floats)

#define SW_M64(row, chunk) ((uint32_t)((row) * 128 + ((((chunk) ^ ((row) & 7)) << 4))))
#define SW_K(row, chunk)   ((uint32_t)((row) * 256 + ((((chunk) ^ ((row) & 7)) << 4))))

__device__ __forceinline__ uint32_t smem_u32(const void* p)
{
    uint32_t a;
    asm("{ .reg .u64 t; cvta.to.shared.u64 t, %1; cvt.u32.u64 %0, t; }" : "=r"(a) : "l"(p));
    return a;
}
__device__ __forceinline__ void cp16(uint32_t dst, const void* src)
{
    asm volatile("cp.async.cg.shared.global [%0], [%1], 16;"
                 :: "r"(dst), "l"(__cvta_generic_to_global(src)));
}
#define CP_COMMIT() asm volatile("cp.async.commit_group;" ::: "memory")
#define CP_WAIT1()  asm volatile("cp.async.wait_group 1;" ::: "memory")
#define CP_WAIT0()  asm volatile("cp.async.wait_group 0;" ::: "memory")

__device__ __forceinline__ void ldsm4(uint32_t& r0, uint32_t& r1, uint32_t& r2, uint32_t& r3,
                                      uint32_t addr)
{
    asm volatile("ldmatrix.sync.aligned.m8n8.x4.shared.b16 {%0,%1,%2,%3}, [%4];"
                 : "=r"(r0), "=r"(r1), "=r"(r2), "=r"(r3) : "r"(addr));
}
__device__ __forceinline__ void ldsm4t(uint32_t& r0, uint32_t& r1, uint32_t& r2, uint32_t& r3,
                                       uint32_t addr)
{
    asm volatile("ldmatrix.sync.aligned.m8n8.x4.trans.shared.b16 {%0,%1,%2,%3}, [%4];"
                 : "=r"(r0), "=r"(r1), "=r"(r2), "=r"(r3) : "r"(addr));
}
__device__ __forceinline__ void mma16(float* d, const uint32_t* a, const uint32_t* b)
{
    asm volatile(
        "mma.sync.aligned.m16n8k16.row.col.f32.f16.f16.f32 "
        "{%0,%1,%2,%3},{%4,%5,%6,%7},{%8,%9},{%0,%1,%2,%3};"
        : "+f"(d[0]), "+f"(d[1]), "+f"(d[2]), "+f"(d[3])
        : "r"(a[0]), "r"(a[1]), "r"(a[2]), "r"(a[3]), "r"(b[0]), "r"(b[1]));
}

__device__ __forceinline__ uint32_t pack2(__half a, __half b)
{
    return ((uint32_t)__half_as_ushort(b) << 16) | (uint32_t)__half_as_ushort(a);
}

// --- staging --------------------------------------------------------------
// m-major 128 rows x 64 k
__device__ __forceinline__ void stage_m64(uint32_t dst, const __half* __restrict__ src,
                                          size_t ld, int row0, int k0, int tid)
{
#pragma unroll
    for (int i = 0; i < 4; ++i) {
        const int idx = tid + (i << 8);
        const int r = idx >> 3;
        const int c = idx & 7;
        cp16(dst + SW_M64(r, c), src + (size_t)(row0 + r) * ld + (size_t)k0 + c * 8);
    }
}
// m-major 64 rows x 64 k
__device__ __forceinline__ void stage_m64h(uint32_t dst, const __half* __restrict__ src,
                                           size_t ld, int row0, int k0, int tid)
{
#pragma unroll
    for (int i = 0; i < 2; ++i) {
        const int idx = tid + (i << 8);
        const int r = idx >> 3;          // 0..63
        const int c = idx & 7;
        cp16(dst + SW_M64(r, c), src + (size_t)(row0 + r) * ld + (size_t)k0 + c * 8);
    }
}
// k-major 64(k) x 128(n)
__device__ __forceinline__ void stage_k64(uint32_t dst, const __half* __restrict__ src,
                                          size_t ld, int j0, int n0, int tid)
{
#pragma unroll
    for (int i = 0; i < 4; ++i) {
        const int idx = tid + (i << 8);
        const int r = idx >> 4;
        const int c = idx & 15;
        cp16(dst + SW_K(r, c), src + (size_t)(j0 + r) * ld + (size_t)n0 + c * 8);
    }
}

// --- compute (k_scores): 128x128 tile, warp 32x64, A/B m-major -------------
__device__ __forceinline__ void compute_mm64(uint32_t sbuf, float d[2][8][4],
                                             int wm, int wn, int lane)
{
    const uint32_t pA = sbuf;
    const uint32_t pB = sbuf + TILE64_B;
    const int arow = wm * 32 + (lane & 15);
    const int brow0 = wn * 64 + ((lane >> 4) << 3) + (lane & 7);
#pragma unroll
    for (int g = 0; g < 4; ++g) {
        const int cA = g * 2 + ((lane >> 4) & 1);
        const int cB = g * 2 + ((lane >> 3) & 1);
        uint32_t ah[2][4];
#pragma unroll
        for (int mt = 0; mt < 2; ++mt)
            ldsm4(ah[mt][0], ah[mt][1], ah[mt][2], ah[mt][3],
                  pA + SW_M64(arow + mt * 16, cA));
#pragma unroll
        for (int p = 0; p < 4; ++p) {
            uint32_t bh[4];
            ldsm4(bh[0], bh[1], bh[2], bh[3], pB + SW_M64(brow0 + p * 16, cB));
#pragma unroll
            for (int mt = 0; mt < 2; ++mt) {
                mma16(d[mt][2 * p],     ah[mt], bh);
                mma16(d[mt][2 * p + 1], ah[mt], bh + 2);
            }
        }
    }
}

// --- compute (k_agg): 64x128 tile, warp 32x32, B k-major trans -------------
__device__ __forceinline__ void compute_mk_s(uint32_t sbuf, float d[2][4][4],
                                             int wm, int wn, int lane)
{
    const uint32_t pA = sbuf;
    const uint32_t pB = sbuf + TILEA_S;
    const int arow = wm * 32 + (lane & 15);
#pragma unroll
    for (int g = 0; g < 4; ++g) {
        const int cA = g * 2 + ((lane >> 4) & 1);
        uint32_t ah[2][4];
#pragma unroll
        for (int mt = 0; mt < 2; ++mt)
            ldsm4(ah[mt][0], ah[mt][1], ah[mt][2], ah[mt][3],
                  pA + SW_M64(arow + mt * 16, cA));
        const int kRow = g * 16 + (lane & 15);
#pragma unroll
        for (int p = 0; p < 2; ++p) {
            const int cB = wn * 4 + p * 2 + ((lane >> 4) & 1);
            uint32_t bh[4];
            ldsm4t(bh[0], bh[1], bh[2], bh[3], pB + SW_K(kRow, cB));
#pragma unroll
            for (int mt = 0; mt < 2; ++mt) {
                mma16(d[mt][2 * p],     ah[mt], bh);
                mma16(d[mt][2 * p + 1], ah[mt], bh + 2);
            }
        }
    }
}

// --- compute (k_out): 64x128 tile, warp 32x32, B m-major -------------------
__device__ __forceinline__ void compute_mm_s(uint32_t sbuf, float d[2][4][4],
                                             int wm, int wn, int lane)
{
    const uint32_t pA = sbuf;
    const uint32_t pB = sbuf + TILEA_S;
    const int arow = wm * 32 + (lane & 15);
    const int brow0 = wn * 32 + ((lane >> 4) << 3) + (lane & 7);
#pragma unroll
    for (int g = 0; g < 4; ++g) {
        const int cA = g * 2 + ((lane >> 4) & 1);
        const int cB = g * 2 + ((lane >> 3) & 1);
        uint32_t ah[2][4];
#pragma unroll
        for (int mt = 0; mt < 2; ++mt)
            ldsm4(ah[mt][0], ah[mt][1], ah[mt][2], ah[mt][3],
                  pA + SW_M64(arow + mt * 16, cA));
#pragma unroll
        for (int p = 0; p < 2; ++p) {
            uint32_t bh[4];
            ldsm4(bh[0], bh[1], bh[2], bh[3], pB + SW_M64(brow0 + p * 16, cB));
#pragma unroll
            for (int mt = 0; mt < 2; ++mt) {
                mma16(d[mt][2 * p],     ah[mt], bh);
                mma16(d[mt][2 * p + 1], ah[mt], bh + 2);
            }
        }
    }
}

// ===========================================================================
// Prep (merged)
// ===========================================================================
__global__ __launch_bounds__(256) void k_prep(const float* __restrict__ x,
                                              const float* __restrict__ wmap,
                                              const float* __restrict__ watt,
                                              const float* __restrict__ wres)
{
    if (blockIdx.x < 4096) {
        const size_t i4 = (size_t)blockIdx.x * 256 + threadIdx.x;
        float4 v = ((const float4*)x)[i4];
        const int dcol = (int)((i4 * 4) & 255);
        float4 w = *(const float4*)(wmap + dcol);
        ((uint2*)g_x_h)[i4] = make_uint2(
            pack2(__float2half_rn(v.x), __float2half_rn(v.y)),
            pack2(__float2half_rn(v.z), __float2half_rn(v.w)));
        ((uint2*)g_xw)[i4] = make_uint2(
            pack2(__float2half_rn(v.x * w.x), __float2half_rn(v.y * w.y)),
            pack2(__float2half_rn(v.z * w.z), __float2half_rn(v.w * w.w)));
    } else {
        const int i = (blockIdx.x - 4096) * 256 + threadIdx.x;
        g_watt_h[i] = __float2half_rn(watt[i]);
        g_wres_h[i] = __float2half_rn(wres[i]);
    }
}

// ===========================================================================
// K1: E = exp((x*wmap) @ x^T), symmetric (lower-tri + mirror), fp16 out.
// ===========================================================================
__global__ __launch_bounds__(256, 2) void k_scores()
{
    extern __shared__ char smx[];
    const uint32_t sb = smem_u32(smx);
    const int tid = threadIdx.x, wid = tid >> 5, lane = tid & 31;
    const int wm = wid >> 1, wn = wid & 1;

    const int b = blockIdx.z;
    int t = blockIdx.x, bx = 0;
    while (t >= 16 - bx) { t -= 16 - bx; ++bx; }
    const int by = bx + t;
    const int m0 = by << 7, n0 = bx << 7;

    const __half* A = g_xw  + (size_t)b * NN * DD;
    const __half* B = g_x_h + (size_t)b * NN * DD;
    __half* Eb = g_attn + (size_t)b * NN * NN;

    float d[2][8][4] = {};
    const int S = 4;
#pragma unroll
    for (int s = 0; s < 2; ++s) {
        const uint32_t nb = sb + s * STG64_B;
        stage_m64(nb, A, DD, m0, s * 64, tid);
        stage_m64(nb + TILE64_B, B, DD, n0, s * 64, tid);
        CP_COMMIT();
    }
#pragma unroll 1
    for (int s = 0; s < S; ++s) {
        if (s < S - 1) CP_WAIT1();
        else CP_WAIT0();
        __syncthreads();
        if (s + 2 < S) {
            const uint32_t nb = sb + ((s + 2) % 3) * STG64_B;
            stage_m64(nb, A, DD, m0, (s + 2) * 64, tid);
            stage_m64(nb + TILE64_B, B, DD, n0, (s + 2) * 64, tid);
            CP_COMMIT();
        }
        compute_mm64(sb + (s % 3) * STG64_B, d, wm, wn, lane);
    }
    __syncthreads();

    const bool mirror = (bx != by);
    __half* st   = (__half*)smx;               // [128][136] fp16 transpose (34816 B)
    float* rsum  = (float*)(smx + 34816);      // [128 rows][8 slots]
    float* csum  = (float*)(smx + 38912);      // [128 cols][32 slots]

    const int rslot = wn * 4 + (lane & 3);
    const int cslot = wm * 8 + (lane >> 2);
    float rp[2][2] = {};
    float cp0[8] = {}, cp1[8] = {};

#pragma unroll
    for (int mt = 0; mt < 2; ++mt) {
        const int rl = wm * 32 + mt * 16 + (lane >> 2);
#pragma unroll
        for (int nt = 0; nt < 8; ++nt) {
            const int cl = wn * 64 + nt * 8 + (lane & 3) * 2;
            float e0 = __expf(d[mt][nt][0]);
            float e1 = __expf(d[mt][nt][1]);
            float e2 = __expf(d[mt][nt][2]);
            float e3 = __expf(d[mt][nt][3]);
            rp[mt][0] += e0 + e1;
            rp[mt][1] += e2 + e3;
            cp0[nt] += e0 + e2;
            cp1[nt] += e1 + e3;
            const __half p0 = __float2half_rn(e0);
            const __half p1 = __float2half_rn(e1);
            const __half p2 = __float2half_rn(e2);
            const __half p3 = __float2half_rn(e3);
            *(uint32_t*)(Eb + (size_t)(m0 + rl) * NN + n0 + cl) = pack2(p0, p1);
            *(uint32_t*)(Eb + (size_t)(m0 + rl + 8) * NN + n0 + cl) = pack2(p2, p3);
            if (mirror) {
                st[(cl + 0) * 136 + rl] = p0;
                st[(cl + 1) * 136 + rl] = p1;
                st[(cl + 0) * 136 + rl + 8] = p2;
                st[(cl + 1) * 136 + rl + 8] = p3;
            }
        }
    }
#pragma unroll
    for (int mt = 0; mt < 2; ++mt) {
        const int rl = wm * 32 + mt * 16 + (lane >> 2);
        rsum[(rl + 0) * 8 + rslot] = rp[mt][0];
        rsum[(rl + 8) * 8 + rslot] = rp[mt][1];
    }
    if (mirror) {
#pragma unroll
        for (int nt = 0; nt < 8; ++nt) {
            const int cl = wn * 64 + nt * 8 + (lane & 3) * 2;
            csum[(cl + 0) * 32 + cslot] = cp0[nt];
            csum[(cl + 1) * 32 + cslot] = cp1[nt];
        }
    }
    __syncthreads();

    if (tid < 128) {
        float s = 0.f;
#pragma unroll
        for (int q = 0; q < 8; ++q) s += rsum[tid * 8 + q];
        g_prow[(((size_t)b * 16 + by) * 128 + tid) * 16 + bx] = s;
    } else if (mirror) {
        const int c = tid - 128;
        float s = 0.f;
#pragma unroll
        for (int q = 0; q < 32; ++q) s += csum[c * 32 + q];
        g_prow[(((size_t)b * 16 + bx) * 128 + c) * 16 + by] = s;
    }

    if (mirror) {
        const int c8 = (tid & 15) << 3;
#pragma unroll
        for (int i = 0; i < 8; ++i) {
            const int rr = (tid >> 4) + (i << 4);
            uint4 v = *(const uint4*)(st + rr * 136 + c8);
            *(uint4*)(Eb + (size_t)(n0 + rr) * NN + m0 + c8) = v;
        }
    }
}

// ===========================================================================
// K3: agg = (E @ x) * invZ — 64x128 tile, occ 3
// ===========================================================================
__global__ __launch_bounds__(256, 3) void k_agg()
{
    extern __shared__ char smx[];
    const uint32_t sb = smem_u32(smx);
    const int tid = threadIdx.x, wid = tid >> 5, lane = tid & 31;
    const int wm = wid >> 2, wn = wid & 3;

    const int b = blockIdx.z;
    const int m0 = blockIdx.y << 6;     // 64-row blocks
    const int n0 = blockIdx.x << 7;

    const __half* A = g_attn + (size_t)b * NN * NN;
    const __half* B = g_x_h + (size_t)b * NN * DD;
    float* ivz = (float*)(smx + SMEM_S);   // [64]

    if (tid < 64) {
        const int rb = m0 >> 7;
        const int rw = (m0 & 127) + tid;
        const float4* p = (const float4*)(g_prow + (((size_t)b * 16 + rb) * 128 + rw) * 16);
        float4 a = p[0], b4 = p[1], c = p[2], e = p[3];
        float s = (a.x + a.y + a.z + a.w) + (b4.x + b4.y + b4.z + b4.w)
                + (c.x + c.y + c.z + c.w) + (e.x + e.y + e.z + e.w);
        ivz[tid] = 1.f / s;
    }

    float d[2][4][4] = {};
    const int S = 32;
#pragma unroll
    for (int s = 0; s < 2; ++s) {
        const uint32_t nb = sb + s * STG_S;
        stage_m64h(nb, A, NN, m0, s * 64, tid);
        stage_k64(nb + TILEA_S, B, DD, s * 64, n0, tid);
        CP_COMMIT();
    }
#pragma unroll 1
    for (int s = 0; s < S; ++s) {
        if (s < S - 1) CP_WAIT1();
        else CP_WAIT0();
        __syncthreads();
        if (s + 2 < S) {
            const uint32_t nb = sb + ((s + 2) % 3) * STG_S;
            stage_m64h(nb, A, NN, m0, (s + 2) * 64, tid);
            stage_k64(nb + TILEA_S, B, DD, (s + 2) * 64, n0, tid);
            CP_COMMIT();
        }
        compute_mk_s(sb + (s % 3) * STG_S, d, wm, wn, lane);
    }

    __half* G = g_agg + (size_t)b * NN * DD;
#pragma unroll
    for (int mt = 0; mt < 2; ++mt) {
        const int rl = wm * 32 + mt * 16 + (lane >> 2);
        const int r0 = m0 + rl;
        const float z0 = ivz[rl];
        const float z1 = ivz[rl + 8];
#pragma unroll
        for (int nt = 0; nt < 4; ++nt) {
            const int c = n0 + wn * 32 + nt * 8 + (lane & 3) * 2;
            const float* dd = d[mt][nt];
            *(uint32_t*)(G + (size_t)r0 * DD + c) =
                pack2(__float2half_rn(dd[0] * z0), __float2half_rn(dd[1] * z0));
            *(uint32_t*)(G + (size_t)(r0 + 8) * DD + c) =
                pack2(__float2half_rn(dd[2] * z1), __float2half_rn(dd[3] * z1));
        }
    }
}

// ===========================================================================
// K4: out(fp16) = agg @ w_att^T + x @ w_res^T — 64x128 tile, occ 3, BN fused
// ===========================================================================
__global__ __launch_bounds__(256, 3) void k_out()
{
    extern __shared__ char smx[];
    const uint32_t sb = smem_u32(smx);
    const int tid = threadIdx.x, wid = tid >> 5, lane = tid & 31;
    const int wm = wid >> 2, wn = wid & 3;

    const int m0 = blockIdx.y << 6;     // 64-row blocks, 256 of them
    const int n0 = blockIdx.x << 7;

    float d[2][4][4] = {};
    const int S = 8;

    auto do_stage = [&](int sn, uint32_t nb) {
        const int k0 = (sn & 3) * 64;
        if (sn < 4) {
            stage_m64h(nb, g_agg, DD, m0, k0, tid);
            stage_m64(nb + TILEA_S, g_watt_h, DD, n0, k0, tid);
        } else {
            stage_m64h(nb, g_x_h, DD, m0, k0, tid);
            stage_m64(nb + TILEA_S, g_wres_h, DD, n0, k0, tid);
        }
        CP_COMMIT();
    };

#pragma unroll
    for (int s = 0; s < 2; ++s) do_stage(s, sb + s * STG_S);
#pragma unroll 1
    for (int s = 0; s < S; ++s) {
        if (s < S - 1) CP_WAIT1();
        else CP_WAIT0();
        __syncthreads();
        if (s + 2 < S) do_stage(s + 2, sb + ((s + 2) % 3) * STG_S);
        compute_mm_s(sb + (s % 3) * STG_S, d, wm, wn, lane);
    }

#pragma unroll
    for (int mt = 0; mt < 2; ++mt) {
#pragma unroll
        for (int nt = 0; nt < 4; ++nt) {
            const int r0 = m0 + wm * 32 + mt * 16 + (lane >> 2);
            const int c = n0 + wn * 32 + nt * 8 + (lane & 3) * 2;
            const float* dd = d[mt][nt];
            *(uint32_t*)(g_outh + (size_t)r0 * DD + c) =
                pack2(__float2half_rn(dd[0]), __float2half_rn(dd[1]));
            *(uint32_t*)(g_outh + (size_t)(r0 + 8) * DD + c) =
                pack2(__float2half_rn(dd[2]), __float2half_rn(dd[3]));
        }
    }

    // fused BN partials: per (64-row block, channel) sum / sumsq
    __syncthreads();
    float* rs = (float*)smx;            // [128 cols][16 slots]
    float* rq = rs + 2048;
    const int slot = wm * 8 + (lane >> 2);
#pragma unroll
    for (int nt = 0; nt < 4; ++nt) {
        const int cl = wn * 32 + nt * 8 + (lane & 3) * 2;
        float s0 = 0.f, s1 = 0.f, q0 = 0.f, q1 = 0.f;
#pragma unroll
        for (int mt = 0; mt < 2; ++mt) {
            const float* dd = d[mt][nt];
            s0 += dd[0] + dd[2];
            s1 += dd[1] + dd[3];
            q0 += dd[0] * dd[0] + dd[2] * dd[2];
            q1 += dd[1] * dd[1] + dd[3] * dd[3];
        }
        rs[(cl + 0) * 16 + slot] = s0;
        rs[(cl + 1) * 16 + slot] = s1;
        rq[(cl + 0) * 16 + slot] = q0;
        rq[(cl + 1) * 16 + slot] = q1;
    }
    __syncthreads();
    if (tid < 128) {
        float S2 = 0.f, Q2 = 0.f;
#pragma unroll
        for (int t = 0; t < 16; ++t) {
            S2 += rs[tid * 16 + t];
            Q2 += rq[tid * 16 + t];
        }
        g_psum[blockIdx.y * 256 + n0 + tid] = S2;
        g_psumsq[blockIdx.y * 256 + n0 + tid] = Q2;
    }
}

// ===========================================================================
// BN stats + SELU
// ===========================================================================
__global__ void k_stats(const float* __restrict__ gamma, const float* __restrict__ beta)
{
    const int c = threadIdx.x;
    float S = 0.f, Q = 0.f;
    for (int t = 0; t < 256; ++t) {
        S += g_psum[t * 256 + c];
        Q += g_psumsq[t * 256 + c];
    }
    const float inv_cnt = 1.f / (float)(BB * NN);
    float mean = S * inv_cnt;
    float var = Q * inv_cnt - mean * mean;
    float sc = gamma[c] * rsqrtf(var + BN_EPS);
    g_scale[c] = sc;
    g_shift[c] = beta[c] - mean * sc;
}

__device__ __forceinline__ float selu_of(float y)
{
    float yc = fminf(fmaxf(y, -10.f), 10.f);
    float neg = SELU_ALPHA * (__expf(yc) - 1.f);
    return SELU_SCALE * (y > 0.f ? y : neg);
}

__global__ __launch_bounds__(256) void k_bnselu(float* __restrict__ out)
{
    const size_t i4 = (size_t)blockIdx.x * 256 + threadIdx.x;
    const int c = (int)((i4 * 4) & 255);
    uint2 raw = *(const uint2*)(g_outh + i4 * 4);
    const __half2* hp = (const __half2*)&raw;
    float2 f0 = __half22float2(hp[0]);
    float2 f1 = __half22float2(hp[1]);
    float4 v;
    v.x = selu_of(f0.x * g_scale[c + 0] + g_shift[c + 0]);
    v.y = selu_of(f0.y * g_scale[c + 1] + g_shift[c + 1]);
    v.z = selu_of(f1.x * g_scale[c + 2] + g_shift[c + 2]);
    v.w = selu_of(f1.y * g_scale[c + 3] + g_shift[c + 3]);
    *(float4*)(out + i4 * 4) = v;
}

// ===========================================================================
extern "C" void kernel_launch(void* const* d_in, const int* in_sizes, int n_in,
                              void* d_out, int out_size)
{
    const float* x     = (const float*)d_in[0];
    const float* wmap  = (const float*)d_in[1];
    const float* watt  = (const float*)d_in[2];
    const float* wres  = (const float*)d_in[3];
    const float* gamma = (const float*)d_in[4];
    const float* beta  = (const float*)d_in[5];
    float* out = (float*)d_out;

    cudaFuncSetAttribute(k_scores, cudaFuncAttributeMaxDynamicSharedMemorySize, SMEM_SC);
    cudaFuncSetAttribute(k_agg,    cudaFuncAttributeMaxDynamicSharedMemorySize, SMEM_AGS);
    cudaFuncSetAttribute(k_out,    cudaFuncAttributeMaxDynamicSharedMemorySize, SMEM_S);

    k_prep<<<4096 + 256, 256>>>(x, wmap, watt, wres);

    k_scores<<<dim3(136, 1, BB), 256, SMEM_SC>>>();

    k_agg<<<dim3(DD / 128, NN / 64, BB), 256, SMEM_AGS>>>();

    k_out<<<dim3(DD / 128, (BB * NN) / 64), 256, SMEM_S>>>();

    k_stats<<<1, 256>>>(gamma, beta);
    k_bnselu<<<(BB * NN * DD) / (256 * 4), 256>>>(out);
}

// round 17
// speedup vs baseline: 1.0997x; 1.0997x over previous
#include <cuda_runtime.h>
#include <cuda_fp16.h>
#include <math.h>
#include <stdint.h>

#define BB 8
#define NN 2048
#define DD 256
#define BN_EPS 1e-5f
#define SELU_ALPHA 1.6732632423543772f
#define SELU_SCALE 1.0507009873554805f

// ===========================================================================
// Scratch (device globals)
// ===========================================================================
__device__ __half g_attn[(size_t)BB * NN * NN];      // 67 MB, UNNORMALIZED exp(s)
__device__ __half g_xw[(size_t)BB * NN * DD];        // A of scores (single)
__device__ __half g_x_h[(size_t)BB * NN * DD];       // fp16(x)
__device__ __half g_agg[(size_t)BB * NN * DD];       // fp16(agg), normalized
__device__ __half g_watt_h[DD * DD];
__device__ __half g_wres_h[DD * DD];
__device__ float g_prow[BB * 16 * 128 * 16];         // [b][rb][row][cb] partials (1 MB)
__device__ float g_psum[128 * 256];
__device__ float g_psumsq[128 * 256];
__device__ float g_scale[256];
__device__ float g_shift[256];

// ===========================================================================
// smem tiles (BK = 64):
// m-major tile: 128 rows x 64 k fp16, 128B rows, chunk' = c ^ (r&7), c in 0..7
// k-major tile: 64 rows(k) x 128 cols(n) fp16, 256B rows, chunk' = c ^ (r&7)
// stage = A(16K) + B(16K) = 32K; 3 buffers = 96K; occ 2
// ===========================================================================
#define TILE64_B 16384
#define STG64_B  32768
#define SMEM_G   (3 * STG64_B)          // 98304
#define SMEM_AGX (SMEM_G + 512)         // + invZ cache

#define SW_M64(row, chunk) ((uint32_t)((row) * 128 + ((((chunk) ^ ((row) & 7)) << 4))))
#define SW_K(row, chunk)   ((uint32_t)((row) * 256 + ((((chunk) ^ ((row) & 7)) << 4))))

__device__ __forceinline__ uint32_t smem_u32(const void* p)
{
    uint32_t a;
    asm("{ .reg .u64 t; cvta.to.shared.u64 t, %1; cvt.u32.u64 %0, t; }" : "=r"(a) : "l"(p));
    return a;
}
__device__ __forceinline__ void cp16(uint32_t dst, const void* src)
{
    asm volatile("cp.async.cg.shared.global [%0], [%1], 16;"
                 :: "r"(dst), "l"(__cvta_generic_to_global(src)));
}
#define CP_COMMIT() asm volatile("cp.async.commit_group;" ::: "memory")
#define CP_WAIT1()  asm volatile("cp.async.wait_group 1;" ::: "memory")
#define CP_WAIT0()  asm volatile("cp.async.wait_group 0;" ::: "memory")

__device__ __forceinline__ void ldsm4(uint32_t& r0, uint32_t& r1, uint32_t& r2, uint32_t& r3,
                                      uint32_t addr)
{
    asm volatile("ldmatrix.sync.aligned.m8n8.x4.shared.b16 {%0,%1,%2,%3}, [%4];"
                 : "=r"(r0), "=r"(r1), "=r"(r2), "=r"(r3) : "r"(addr));
}
__device__ __forceinline__ void ldsm4t(uint32_t& r0, uint32_t& r1, uint32_t& r2, uint32_t& r3,
                                       uint32_t addr)
{
    asm volatile("ldmatrix.sync.aligned.m8n8.x4.trans.shared.b16 {%0,%1,%2,%3}, [%4];"
                 : "=r"(r0), "=r"(r1), "=r"(r2), "=r"(r3) : "r"(addr));
}
__device__ __forceinline__ void mma16(float* d, const uint32_t* a, const uint32_t* b)
{
    asm volatile(
        "mma.sync.aligned.m16n8k16.row.col.f32.f16.f16.f32 "
        "{%0,%1,%2,%3},{%4,%5,%6,%7},{%8,%9},{%0,%1,%2,%3};"
        : "+f"(d[0]), "+f"(d[1]), "+f"(d[2]), "+f"(d[3])
        : "r"(a[0]), "r"(a[1]), "r"(a[2]), "r"(a[3]), "r"(b[0]), "r"(b[1]));
}

__device__ __forceinline__ uint32_t pack2(__half a, __half b)
{
    return ((uint32_t)__half_as_ushort(b) << 16) | (uint32_t)__half_as_ushort(a);
}

// --- staging (BK=64) ----------------------------------------------------
__device__ __forceinline__ void stage_m64(uint32_t dst, const __half* __restrict__ src,
                                          size_t ld, int row0, int k0, int tid)
{
#pragma unroll
    for (int i = 0; i < 4; ++i) {
        const int idx = tid + (i << 8);
        const int r = idx >> 3;          // 0..127
        const int c = idx & 7;           // 0..7
        cp16(dst + SW_M64(r, c), src + (size_t)(row0 + r) * ld + (size_t)k0 + c * 8);
    }
}
__device__ __forceinline__ void stage_k64(uint32_t dst, const __half* __restrict__ src,
                                          size_t ld, int j0, int n0, int tid)
{
#pragma unroll
    for (int i = 0; i < 4; ++i) {
        const int idx = tid + (i << 8);
        const int r = idx >> 4;          // 0..63 k row
        const int c = idx & 15;          // 0..15 n chunk of 8
        cp16(dst + SW_K(r, c), src + (size_t)(j0 + r) * ld + (size_t)n0 + c * 8);
    }
}

// --- compute BK=64: A m-major, B m-major ---------------------------------
__device__ __forceinline__ void compute_mm64(uint32_t sbuf, float d[2][8][4],
                                             int wm, int wn, int lane)
{
    const uint32_t pA = sbuf;
    const uint32_t pB = sbuf + TILE64_B;
    const int arow = wm * 32 + (lane & 15);
    const int brow0 = wn * 64 + ((lane >> 4) << 3) + (lane & 7);
#pragma unroll
    for (int g = 0; g < 4; ++g) {
        const int cA = g * 2 + ((lane >> 4) & 1);
        const int cB = g * 2 + ((lane >> 3) & 1);
        uint32_t ah[2][4];
#pragma unroll
        for (int mt = 0; mt < 2; ++mt) {
            const uint32_t a = pA + SW_M64(arow + mt * 16, cA);
            ldsm4(ah[mt][0], ah[mt][1], ah[mt][2], ah[mt][3], a);
        }
#pragma unroll
        for (int p = 0; p < 4; ++p) {
            const uint32_t bo = SW_M64(brow0 + p * 16, cB);
            uint32_t bh[4];
            ldsm4(bh[0], bh[1], bh[2], bh[3], pB + bo);
#pragma unroll
            for (int mt = 0; mt < 2; ++mt) {
                mma16(d[mt][2 * p],     ah[mt], bh);
                mma16(d[mt][2 * p + 1], ah[mt], bh + 2);
            }
        }
    }
}

// --- compute BK=64: A m-major, B k-major via trans (k_agg) ---------------
__device__ __forceinline__ void compute_mk64(uint32_t sbuf, float d[2][8][4],
                                             int wm, int wn, int lane)
{
    const uint32_t pA = sbuf;
    const uint32_t pB = sbuf + TILE64_B;
    const int arow = wm * 32 + (lane & 15);
#pragma unroll
    for (int g = 0; g < 4; ++g) {
        const int cA = g * 2 + ((lane >> 4) & 1);
        uint32_t ah[2][4];
#pragma unroll
        for (int mt = 0; mt < 2; ++mt) {
            const uint32_t a = pA + SW_M64(arow + mt * 16, cA);
            ldsm4(ah[mt][0], ah[mt][1], ah[mt][2], ah[mt][3], a);
        }
        const int kRow = g * 16 + (lane & 15);
#pragma unroll
        for (int p = 0; p < 4; ++p) {
            const int cB = wn * 8 + p * 2 + ((lane >> 4) & 1);
            const uint32_t bo = SW_K(kRow, cB);
            uint32_t bh[4];
            ldsm4t(bh[0], bh[1], bh[2], bh[3], pB + bo);
#pragma unroll
            for (int mt = 0; mt < 2; ++mt) {
                mma16(d[mt][2 * p],     ah[mt], bh);
                mma16(d[mt][2 * p + 1], ah[mt], bh + 2);
            }
        }
    }
}

// ===========================================================================
// Prep (merged): blocks 0..4095 convert x; blocks 4096..4351 convert weights
// ===========================================================================
__global__ __launch_bounds__(256) void k_prep(const float* __restrict__ x,
                                              const float* __restrict__ wmap,
                                              const float* __restrict__ watt,
                                              const float* __restrict__ wres)
{
    if (blockIdx.x < 4096) {
        const size_t i4 = (size_t)blockIdx.x * 256 + threadIdx.x;
        float4 v = ((const float4*)x)[i4];
        const int dcol = (int)((i4 * 4) & 255);
        float4 w = *(const float4*)(wmap + dcol);
        ((uint2*)g_x_h)[i4] = make_uint2(
            pack2(__float2half_rn(v.x), __float2half_rn(v.y)),
            pack2(__float2half_rn(v.z), __float2half_rn(v.w)));
        ((uint2*)g_xw)[i4] = make_uint2(
            pack2(__float2half_rn(v.x * w.x), __float2half_rn(v.y * w.y)),
            pack2(__float2half_rn(v.z * w.z), __float2half_rn(v.w * w.w)));
    } else {
        const int i = (blockIdx.x - 4096) * 256 + threadIdx.x;   // < 65536
        g_watt_h[i] = __float2half_rn(watt[i]);
        g_wres_h[i] = __float2half_rn(wres[i]);
    }
}

// ===========================================================================
// K1: E = exp((x*wmap) @ x^T), symmetric (lower-tri + mirror), fp16 out.
// Emits per-(rowblock,colblock) row sums of E into g_prow[b][rb][row][cb].
// ===========================================================================
__global__ __launch_bounds__(256, 2) void k_scores()
{
    extern __shared__ char smx[];
    const uint32_t sb = smem_u32(smx);
    const int tid = threadIdx.x, wid = tid >> 5, lane = tid & 31;
    const int wm = wid >> 1, wn = wid & 1;

    const int b = blockIdx.z;
    int t = blockIdx.x, bx = 0;
    while (t >= 16 - bx) { t -= 16 - bx; ++bx; }
    const int by = bx + t;
    const int m0 = by << 7, n0 = bx << 7;

    const __half* A = g_xw  + (size_t)b * NN * DD;
    const __half* B = g_x_h + (size_t)b * NN * DD;
    __half* Eb = g_attn + (size_t)b * NN * NN;

    float d[2][8][4] = {};
    const int S = 4;
#pragma unroll
    for (int s = 0; s < 2; ++s) {
        const uint32_t nb = sb + s * STG64_B;
        stage_m64(nb, A, DD, m0, s * 64, tid);
        stage_m64(nb + TILE64_B, B, DD, n0, s * 64, tid);
        CP_COMMIT();
    }
#pragma unroll 1
    for (int s = 0; s < S; ++s) {
        if (s < S - 1) CP_WAIT1();
        else CP_WAIT0();
        __syncthreads();
        if (s + 2 < S) {
            const uint32_t nb = sb + ((s + 2) % 3) * STG64_B;
            stage_m64(nb, A, DD, m0, (s + 2) * 64, tid);
            stage_m64(nb + TILE64_B, B, DD, n0, (s + 2) * 64, tid);
            CP_COMMIT();
        }
        compute_mm64(sb + (s % 3) * STG64_B, d, wm, wn, lane);
    }
    __syncthreads();

    const bool mirror = (bx != by);
    __half* st   = (__half*)smx;               // [128][136] fp16 transpose (34816 B)
    float* rsum  = (float*)(smx + 34816);      // [128 rows][8 slots]  (4096 B)
    float* csum  = (float*)(smx + 38912);      // [128 cols][32 slots] (16384 B)

    const int rslot = wn * 4 + (lane & 3);
    const int cslot = wm * 8 + (lane >> 2);
    float rp[2][2] = {};
    float cp0[8] = {}, cp1[8] = {};

#pragma unroll
    for (int mt = 0; mt < 2; ++mt) {
        const int rl = wm * 32 + mt * 16 + (lane >> 2);
#pragma unroll
        for (int nt = 0; nt < 8; ++nt) {
            const int cl = wn * 64 + nt * 8 + (lane & 3) * 2;
            float e0 = __expf(d[mt][nt][0]);
            float e1 = __expf(d[mt][nt][1]);
            float e2 = __expf(d[mt][nt][2]);
            float e3 = __expf(d[mt][nt][3]);
            rp[mt][0] += e0 + e1;
            rp[mt][1] += e2 + e3;
            cp0[nt] += e0 + e2;
            cp1[nt] += e1 + e3;
            const __half p0 = __float2half_rn(e0);
            const __half p1 = __float2half_rn(e1);
            const __half p2 = __float2half_rn(e2);
            const __half p3 = __float2half_rn(e3);
            *(uint32_t*)(Eb + (size_t)(m0 + rl) * NN + n0 + cl) = pack2(p0, p1);
            *(uint32_t*)(Eb + (size_t)(m0 + rl + 8) * NN + n0 + cl) = pack2(p2, p3);
            if (mirror) {
                st[(cl + 0) * 136 + rl] = p0;
                st[(cl + 1) * 136 + rl] = p1;
                st[(cl + 0) * 136 + rl + 8] = p2;
                st[(cl + 1) * 136 + rl + 8] = p3;
            }
        }
    }
#pragma unroll
    for (int mt = 0; mt < 2; ++mt) {
        const int rl = wm * 32 + mt * 16 + (lane >> 2);
        rsum[(rl + 0) * 8 + rslot] = rp[mt][0];
        rsum[(rl + 8) * 8 + rslot] = rp[mt][1];
    }
    if (mirror) {
#pragma unroll
        for (int nt = 0; nt < 8; ++nt) {
            const int cl = wn * 64 + nt * 8 + (lane & 3) * 2;
            csum[(cl + 0) * 32 + cslot] = cp0[nt];
            csum[(cl + 1) * 32 + cslot] = cp1[nt];
        }
    }
    __syncthreads();

    if (tid < 128) {
        float s = 0.f;
#pragma unroll
        for (int q = 0; q < 8; ++q) s += rsum[tid * 8 + q];
        g_prow[(((size_t)b * 16 + by) * 128 + tid) * 16 + bx] = s;
    } else if (mirror) {
        const int c = tid - 128;
        float s = 0.f;
#pragma unroll
        for (int q = 0; q < 32; ++q) s += csum[c * 32 + q];
        g_prow[(((size_t)b * 16 + bx) * 128 + c) * 16 + by] = s;
    }

    if (mirror) {
        const int c8 = (tid & 15) << 3;
#pragma unroll
        for (int i = 0; i < 8; ++i) {
            const int rr = (tid >> 4) + (i << 4);
            uint4 v = *(const uint4*)(st + rr * 136 + c8);
            *(uint4*)(Eb + (size_t)(n0 + rr) * NN + m0 + c8) = v;
        }
    }
}

// ===========================================================================
// K3: agg = (E @ x) * invZ  (A = E m-major, B = x k-major/trans)
// invZ computed in-kernel from g_prow partials.
// ===========================================================================
__global__ __launch_bounds__(256, 2) void k_agg()
{
    extern __shared__ char smx[];
    const uint32_t sb = smem_u32(smx);
    const int tid = threadIdx.x, wid = tid >> 5, lane = tid & 31;
    const int wm = wid >> 1, wn = wid & 1;

    const int b = blockIdx.z;
    const int m0 = blockIdx.y << 7;
    const int n0 = blockIdx.x << 7;

    const __half* A = g_attn + (size_t)b * NN * NN;
    const __half* B = g_x_h + (size_t)b * NN * DD;
    float* ivz = (float*)(smx + SMEM_G);   // [128]

    if (tid < 128) {
        const float4* p = (const float4*)(g_prow + ((size_t)(b * 16) + (m0 >> 7)) * 128 * 16
                                          + (size_t)tid * 16);
        float4 a = p[0], b4 = p[1], c = p[2], e = p[3];
        float s = (a.x + a.y + a.z + a.w) + (b4.x + b4.y + b4.z + b4.w)
                + (c.x + c.y + c.z + c.w) + (e.x + e.y + e.z + e.w);
        ivz[tid] = 1.f / s;
    }

    float d[2][8][4] = {};
    const int S = 32;
#pragma unroll
    for (int s = 0; s < 2; ++s) {
        const uint32_t nb = sb + s * STG64_B;
        stage_m64(nb, A, NN, m0, s * 64, tid);
        stage_k64(nb + TILE64_B, B, DD, s * 64, n0, tid);
        CP_COMMIT();
    }
#pragma unroll 1
    for (int s = 0; s < S; ++s) {
        if (s < S - 1) CP_WAIT1();
        else CP_WAIT0();
        __syncthreads();
        if (s + 2 < S) {
            const uint32_t nb = sb + ((s + 2) % 3) * STG64_B;
            stage_m64(nb, A, NN, m0, (s + 2) * 64, tid);
            stage_k64(nb + TILE64_B, B, DD, (s + 2) * 64, n0, tid);
            CP_COMMIT();
        }
        compute_mk64(sb + (s % 3) * STG64_B, d, wm, wn, lane);
    }

    __half* G = g_agg + (size_t)b * NN * DD;
#pragma unroll
    for (int mt = 0; mt < 2; ++mt) {
        const int rl = wm * 32 + mt * 16 + (lane >> 2);
        const int r0 = m0 + rl;
        const float z0 = ivz[rl];
        const float z1 = ivz[rl + 8];
#pragma unroll
        for (int nt = 0; nt < 8; ++nt) {
            const int c = n0 + wn * 64 + nt * 8 + (lane & 3) * 2;
            const float* dd = d[mt][nt];
            *(uint32_t*)(G + (size_t)r0 * DD + c) =
                pack2(__float2half_rn(dd[0] * z0), __float2half_rn(dd[1] * z0));
            *(uint32_t*)(G + (size_t)(r0 + 8) * DD + c) =
                pack2(__float2half_rn(dd[2] * z1), __float2half_rn(dd[3] * z1));
        }
    }
}

// ===========================================================================
// K4: out = agg @ w_att^T + x @ w_res^T, with fused per-block BN partials
// ===========================================================================
__global__ __launch_bounds__(256, 2) void k_out(float* __restrict__ out)
{
    extern __shared__ char smx[];
    const uint32_t sb = smem_u32(smx);
    const int tid = threadIdx.x, wid = tid >> 5, lane = tid & 31;
    const int wm = wid >> 1, wn = wid & 1;

    const int m0 = blockIdx.y << 7;
    const int n0 = blockIdx.x << 7;

    float d[2][8][4] = {};
    const int S = 8;

    auto do_stage = [&](int sn, uint32_t nb) {
        const int k0 = (sn & 3) * 64;
        if (sn < 4) {
            stage_m64(nb, g_agg, DD, m0, k0, tid);
            stage_m64(nb + TILE64_B, g_watt_h, DD, n0, k0, tid);
        } else {
            stage_m64(nb, g_x_h, DD, m0, k0, tid);
            stage_m64(nb + TILE64_B, g_wres_h, DD, n0, k0, tid);
        }
        CP_COMMIT();
    };

#pragma unroll
    for (int s = 0; s < 2; ++s) do_stage(s, sb + s * STG64_B);
#pragma unroll 1
    for (int s = 0; s < S; ++s) {
        if (s < S - 1) CP_WAIT1();
        else CP_WAIT0();
        __syncthreads();
        if (s + 2 < S) do_stage(s + 2, sb + ((s + 2) % 3) * STG64_B);
        compute_mm64(sb + (s % 3) * STG64_B, d, wm, wn, lane);
    }

#pragma unroll
    for (int mt = 0; mt < 2; ++mt) {
#pragma unroll
        for (int nt = 0; nt < 8; ++nt) {
            const int r0 = m0 + wm * 32 + mt * 16 + (lane >> 2);
            const int c = n0 + wn * 64 + nt * 8 + (lane & 3) * 2;
            const float* dd = d[mt][nt];
            *(float2*)(out + (size_t)r0 * DD + c) = make_float2(dd[0], dd[1]);
            *(float2*)(out + (size_t)(r0 + 8) * DD + c) = make_float2(dd[2], dd[3]);
        }
    }

    // fused BN partials: per (m-block, channel) sum / sumsq
    __syncthreads();
    float* rs = (float*)smx;            // [128 cols][32 slots]
    float* rq = rs + 4096;
    const int slot = wm * 8 + (lane >> 2);
#pragma unroll
    for (int nt = 0; nt < 8; ++nt) {
        const int cl = wn * 64 + nt * 8 + (lane & 3) * 2;
        float s0 = 0.f, s1 = 0.f, q0 = 0.f, q1 = 0.f;
#pragma unroll
        for (int mt = 0; mt < 2; ++mt) {
            const float* dd = d[mt][nt];
            s0 += dd[0] + dd[2];
            s1 += dd[1] + dd[3];
            q0 += dd[0] * dd[0] + dd[2] * dd[2];
            q1 += dd[1] * dd[1] + dd[3] * dd[3];
        }
        rs[(cl + 0) * 32 + slot] = s0;
        rs[(cl + 1) * 32 + slot] = s1;
        rq[(cl + 0) * 32 + slot] = q0;
        rq[(cl + 1) * 32 + slot] = q1;
    }
    __syncthreads();
    if (tid < 128) {
        float S2 = 0.f, Q2 = 0.f;
#pragma unroll
        for (int t = 0; t < 32; ++t) {
            S2 += rs[tid * 32 + t];
            Q2 += rq[tid * 32 + t];
        }
        g_psum[blockIdx.y * 256 + n0 + tid] = S2;
        g_psumsq[blockIdx.y * 256 + n0 + tid] = Q2;
    }
}

// ===========================================================================
// BN stats + SELU
// ===========================================================================
__global__ void k_stats(const float* __restrict__ gamma, const float* __restrict__ beta)
{
    const int c = threadIdx.x;
    float S = 0.f, Q = 0.f;
    for (int t = 0; t < 128; ++t) {
        S += g_psum[t * 256 + c];
        Q += g_psumsq[t * 256 + c];
    }
    const float inv_cnt = 1.f / (float)(BB * NN);
    float mean = S * inv_cnt;
    float var = Q * inv_cnt - mean * mean;
    float sc = gamma[c] * rsqrtf(var + BN_EPS);
    g_scale[c] = sc;
    g_shift[c] = beta[c] - mean * sc;
}

__device__ __forceinline__ float selu_of(float v, int c)
{
    float y = v * g_scale[c] + g_shift[c];
    float yc = fminf(fmaxf(y, -10.f), 10.f);
    float neg = SELU_ALPHA * (__expf(yc) - 1.f);
    return SELU_SCALE * (y > 0.f ? y : neg);
}

__global__ __launch_bounds__(256) void k_bnselu(float* __restrict__ out)
{
    size_t i4 = (size_t)blockIdx.x * 256 + threadIdx.x;
    float4 v = *(float4*)(out + i4 * 4);
    int c = (int)((i4 * 4) & 255);
    v.x = selu_of(v.x, c + 0);
    v.y = selu_of(v.y, c + 1);
    v.z = selu_of(v.z, c + 2);
    v.w = selu_of(v.w, c + 3);
    *(float4*)(out + i4 * 4) = v;
}

// ===========================================================================
extern "C" void kernel_launch(void* const* d_in, const int* in_sizes, int n_in,
                              void* d_out, int out_size)
{
    const float* x     = (const float*)d_in[0];
    const float* wmap  = (const float*)d_in[1];
    const float* watt  = (const float*)d_in[2];
    const float* wres  = (const float*)d_in[3];
    const float* gamma = (const float*)d_in[4];
    const float* beta  = (const float*)d_in[5];
    float* out = (float*)d_out;

    cudaFuncSetAttribute(k_scores, cudaFuncAttributeMaxDynamicSharedMemorySize, SMEM_G);
    cudaFuncSetAttribute(k_agg,    cudaFuncAttributeMaxDynamicSharedMemorySize, SMEM_AGX);
    cudaFuncSetAttribute(k_out,    cudaFuncAttributeMaxDynamicSharedMemorySize, SMEM_G);

    k_prep<<<4096 + 256, 256>>>(x, wmap, watt, wres);

    k_scores<<<dim3(136, 1, BB), 256, SMEM_G>>>();

    k_agg<<<dim3(DD / 128, NN / 128, BB), 256, SMEM_AGX>>>();

    k_out<<<dim3(DD / 128, (BB * NN) / 128), 256, SMEM_G>>>(out);

    k_stats<<<1, 256>>>(gamma, beta);
    k_bnselu<<<(BB * NN * DD) / (256 * 4), 256>>>(out);
}